// round 8
// baseline (speedup 1.0000x reference)
#include <cuda_runtime.h>
#include <cstdint>

// CRF forward (logZ) + Viterbi, one warp EACH per batch (2 warps/block).
// R7's cheap chains (ratio-renormalized exp-domain forward; exact fmax-tree
// + eq-bitmap Viterbi) + power-of-2 renormalizer (no rcp, no per-step log).
// Counted loops via binary-searched length (mask monotone).
// out (f32): [0,B) logZ, [B,2B) best_score, [2B, 2B+S*B*T) pointers.

constexpr int S = 1024, B = 1024, T = 32;
#define NEG_INF   (-10000.0f)
#define START_TAG 29
#define STOP_TAG  30

__device__ __forceinline__ void ffma2(unsigned long long& d, unsigned long long a, unsigned long long b) {
    asm("fma.rn.f32x2 %0, %1, %2, %0;" : "+l"(d) : "l"(a), "l"(b));
}
__device__ __forceinline__ unsigned long long fadd2(unsigned long long a, unsigned long long b) {
    unsigned long long r;
    asm("add.rn.f32x2 %0, %1, %2;" : "=l"(r) : "l"(a), "l"(b));
    return r;
}
__device__ __forceinline__ unsigned long long pack2(float lo, float hi) {
    unsigned long long r;
    asm("mov.b64 %0, {%1, %2};" : "=l"(r) : "f"(lo), "f"(hi));
    return r;
}
__device__ __forceinline__ void unpack2(unsigned long long v, float& lo, float& hi) {
    asm("mov.b64 {%0, %1}, %2;" : "=f"(lo), "=f"(hi) : "l"(v));
}

__global__ void __launch_bounds__(64) crf_kernel(
    const float* __restrict__ feats, const float* __restrict__ mask,
    const float* __restrict__ trans, float* __restrict__ out)
{
    __shared__ __align__(16) float Eb[2][T];   // forward exp-state (warp 0 only)
    __shared__ __align__(16) float Sb[2][T];   // viterbi scores    (warp 1 only)

    const int lane = threadIdx.x & 31;
    const int warp = threadIdx.x >> 5;
    const int b    = blockIdx.x;

    // length = first s with mask[s][b]==0 (mask monotone). One-time search.
    int lo = 0, hi = S;
    #pragma unroll 1
    while (lo < hi) {
        const int mid = (lo + hi) >> 1;
        if (__ldg(mask + (size_t)mid * B + b) != 0.0f) lo = mid + 1; else hi = mid;
    }
    const int len = lo;

    const float L2E = 1.4426950408889634f;
    const float LN2 = 0.6931471805599453f;
    const float tstop = __ldg(trans + STOP_TAG * T + lane);

    const size_t BT = (size_t)B * T;
    const float* fp = feats + (size_t)b * T + lane;
    float fq[4];
    #pragma unroll
    for (int k = 0; k < 4; k++) fq[k] = __ldg(fp + (size_t)k * BT);

    if (warp == 0) {
        // ================= Forward: log partition =================
        // W_ij = exp(t_ij); forbidden -1e4 entries underflow to exactly 0.
        unsigned long long W2[T / 2];
        #pragma unroll
        for (int k = 0; k < T / 2; k++)
            W2[k] = pack2(__expf(__ldg(trans + lane * T + 2 * k)),
                          __expf(__ldg(trans + lane * T + 2 * k + 1)));

        float Ev = (lane == START_TAG) ? 1.0f : 0.0f;   // exp(alpha0 - 0)
        float O  = 0.0f;                                 // alpha = log(E) + O

        Eb[0][lane] = Ev;
        __syncwarp();

        #pragma unroll 4
        for (int s = 0; s < len; s++) {
            const int j  = s & 3;
            const int pb = s & 1;
            const float fv = fq[j];
            const int pfr = (s + 4 < S) ? (s + 4) : (S - 1);
            fq[j] = __ldg(fp + (size_t)pfr * BT);       // forced MLP=4

            const float fv0 = __shfl_sync(0xffffffffu, fv, 0);
            float X;                                     // exp(fv - fv0), bounded
            asm("ex2.approx.ftz.f32 %0, %1;" : "=f"(X) : "f"((fv - fv0) * L2E));

            const ulonglong2* e2 = (const ulonglong2*)Eb[pb];
            unsigned long long a0 = 0ull, a1 = 0ull, a2 = 0ull, a3 = 0ull;
            #pragma unroll
            for (int k = 0; k < 4; k++) {
                const ulonglong2 qa = e2[2 * k];
                const ulonglong2 qb = e2[2 * k + 1];
                ffma2(a0, qa.x, W2[4 * k]);
                ffma2(a1, qa.y, W2[4 * k + 1]);
                ffma2(a2, qb.x, W2[4 * k + 2]);
                ffma2(a3, qb.y, W2[4 * k + 3]);
            }
            const unsigned long long sAB = fadd2(fadd2(a0, a1), fadd2(a2, a3));
            float sl, sh; unpack2(sAB, sl, sh);
            const float sum = sl + sh;                   // sum_0 > 0 always

            // Power-of-2 renormalization: e = exponent(sum_0); E' = sum*2^-e*X.
            const int s0b = __shfl_sync(0xffffffffu, __float_as_int(sum), 0);
            const int e   = (s0b >> 23) - 127;           // sum_0 in [1,2)*2^e
            const float g = __int_as_float((127 - e) << 23);   // exact 2^-e
            Ev = (sum * g) * X;

            Eb[pb ^ 1][lane] = Ev;
            __syncwarp();

            O = fmaf((float)e, LN2, O + fv0);            // off-chain, exact e*ln2
        }

        // logZ = O + log( sum_i E_i * exp(tstop_i) )  (E bounded)
        float z = Ev * __expf(tstop);
        #pragma unroll
        for (int o = 16; o; o >>= 1)
            z += __shfl_xor_sync(0xffffffffu, z, o);
        if (lane == 0) out[b] = O + __logf(z);
    } else {
        // ================= Viterbi: max score + pointers =================
        float tr[T];
        #pragma unroll
        for (int h = 0; h < T; h++)
            tr[h] = __ldg(trans + lane * T + h);

        float sc = (lane == START_TAG) ? 0.0f : NEG_INF;
        Sb[0][lane] = sc;
        __syncwarp();

        float* pout = out + 2 * B + (size_t)b * T + lane;

        #pragma unroll 4
        for (int s = 0; s < len; s++) {
            const int j  = s & 3;
            const int pb = s & 1;
            const float fv = fq[j];
            const int pfr = (s + 4 < S) ? (s + 4) : (S - 1);
            fq[j] = __ldg(fp + (size_t)pfr * BT);

            const float4* s4 = (const float4*)Sb[pb];
            float vv[T];
            #pragma unroll
            for (int k = 0; k < 8; k++) {
                const float4 q = s4[k];
                vv[4 * k]     = q.x + tr[4 * k];
                vv[4 * k + 1] = q.y + tr[4 * k + 1];
                vv[4 * k + 2] = q.z + tr[4 * k + 2];
                vv[4 * k + 3] = q.w + tr[4 * k + 3];
            }
            float mx[16];
            #pragma unroll
            for (int i = 0; i < 16; i++) mx[i] = fmaxf(vv[i], vv[i + 16]);
            #pragma unroll
            for (int off = 8; off; off >>= 1)
                #pragma unroll
                for (int i = 0; i < 8; i++)
                    if (i < off) mx[i] = fmaxf(mx[i], mx[i + off]);
            const float vmax = mx[0];
            sc = vmax + fv;                              // exact update

            Sb[pb ^ 1][lane] = sc;
            __syncwarp();

            // off-chain: exact first-index argmax + pointer store
            unsigned eq = 0;
            #pragma unroll
            for (int h = 0; h < T; h++)
                if (vv[h] == vmax) eq |= (1u << h);
            __stcs(pout, (float)(__ffs(eq) - 1));
            pout += BT;
        }

        if (len < S) {
            // Frozen scores: Sb[len&1] holds final sc. One more argmax = tail ptr.
            const float4* s4 = (const float4*)Sb[len & 1];
            float vv[T];
            #pragma unroll
            for (int k = 0; k < 8; k++) {
                const float4 q = s4[k];
                vv[4 * k]     = q.x + tr[4 * k];
                vv[4 * k + 1] = q.y + tr[4 * k + 1];
                vv[4 * k + 2] = q.z + tr[4 * k + 2];
                vv[4 * k + 3] = q.w + tr[4 * k + 3];
            }
            float mx[16];
            #pragma unroll
            for (int i = 0; i < 16; i++) mx[i] = fmaxf(vv[i], vv[i + 16]);
            #pragma unroll
            for (int off = 8; off; off >>= 1)
                #pragma unroll
                for (int i = 0; i < 8; i++)
                    if (i < off) mx[i] = fmaxf(mx[i], mx[i + off]);
            const float vmax = mx[0];
            unsigned eq = 0;
            #pragma unroll
            for (int h = 0; h < T; h++)
                if (vv[h] == vmax) eq |= (1u << h);
            const float pv = (float)(__ffs(eq) - 1);
            #pragma unroll 4
            for (int s = len; s < S; s++) { __stcs(pout, pv); pout += BT; }
        }

        // best_score = max(sc + t[STOP,:])
        float v = sc + tstop;
        #pragma unroll
        for (int o = 16; o; o >>= 1)
            v = fmaxf(v, __shfl_xor_sync(0xffffffffu, v, o));
        if (lane == 0) out[B + b] = v;
    }
}

extern "C" void kernel_launch(void* const* d_in, const int* in_sizes, int n_in,
                              void* d_out, int out_size) {
    const float* feats = (const float*)d_in[0];
    const float* mask  = (const float*)d_in[1];
    const float* trans = (const float*)d_in[2];
    crf_kernel<<<B, 64>>>(feats, mask, trans, (float*)d_out);
}